// round 1
// baseline (speedup 1.0000x reference)
#include <cuda_runtime.h>
#include <cstdint>

// Problem geometry: velocity (B=2, D=128, H=128, W=128, C=3) float32
#define B_  2
#define DIM 128
#define VOX_PER_B (DIM * DIM * DIM)          // 2097152 = 1<<21
#define N_VOX (B_ * VOX_PER_B)               // 4194304
#define N_ELEM (N_VOX * 3)                   // 12582912

// Ping-pong scratch (allocation-free: __device__ globals)
__device__ float g_bufA[N_ELEM];
__device__ float g_bufB[N_ELEM];

// MODE: 0 = first iter (scale input by 1/2^STEPS), 1 = middle, 2 = last (add identity grid, write d_out)
template <int MODE>
__global__ __launch_bounds__(256)
void gridexp_step(const float* __restrict__ src, float* __restrict__ dst, float scale)
{
    int idx = blockIdx.x * blockDim.x + threadIdx.x;
    if (idx >= N_VOX) return;

    int b = idx >> 21;
    int r = idx & (VOX_PER_B - 1);
    int z = r >> 14;
    int y = (r >> 7) & 127;
    int x = r & 127;

    const float* p = src + (size_t)idx * 3;
    float vz = p[0], vy = p[1], vx = p[2];
    if (MODE == 0) { vz *= scale; vy *= scale; vx *= scale; }

    // phi = identity + v (voxel coords, z/y/x channel order)
    float phz = (float)z + vz;
    float phy = (float)y + vy;
    float phx = (float)x + vx;

    float fz = floorf(phz), fy = floorf(phy), fx = floorf(phx);
    float wz1 = phz - fz, wy1 = phy - fy, wx1 = phx - fx;
    float wz0 = 1.0f - wz1, wy0 = 1.0f - wy1, wx0 = 1.0f - wx1;

    int z0 = ((int)fz) & 127, z1 = (z0 + 1) & 127;
    int y0 = ((int)fy) & 127, y1 = (y0 + 1) & 127;
    int x0 = ((int)fx) & 127, x1 = (x0 + 1) & 127;

    int base = b << 21;
    int zo[2] = { z0 << 14, z1 << 14 };
    int yo[2] = { y0 << 7,  y1 << 7  };
    int xo[2] = { x0,       x1       };
    float wz[2] = { wz0, wz1 };
    float wy[2] = { wy0, wy1 };
    float wx[2] = { wx0, wx1 };

    float sz = 0.0f, sy = 0.0f, sx = 0.0f;
#pragma unroll
    for (int a = 0; a < 2; ++a) {
#pragma unroll
        for (int c = 0; c < 2; ++c) {
#pragma unroll
            for (int d = 0; d < 2; ++d) {
                int lin = base + zo[a] + yo[c] + xo[d];
                const float* q = src + (size_t)lin * 3;
                float w = wz[a] * wy[c] * wx[d];
                sz += w * __ldg(q + 0);
                sy += w * __ldg(q + 1);
                sx += w * __ldg(q + 2);
            }
        }
    }
    if (MODE == 0) { sz *= scale; sy *= scale; sx *= scale; }

    float oz = vz + sz;
    float oy = vy + sy;
    float ox = vx + sx;
    if (MODE == 2) { oz += (float)z; oy += (float)y; ox += (float)x; }

    float* o = dst + (size_t)idx * 3;
    o[0] = oz; o[1] = oy; o[2] = ox;
}

extern "C" void kernel_launch(void* const* d_in, const int* in_sizes, int n_in,
                              void* d_out, int out_size)
{
    (void)in_sizes; (void)n_in; (void)out_size;
    const float* vel = (const float*)d_in[0];
    float* out = (float*)d_out;

    float* bufA = nullptr;
    float* bufB = nullptr;
    cudaGetSymbolAddress((void**)&bufA, g_bufA);
    cudaGetSymbolAddress((void**)&bufB, g_bufB);

    const float scale = 1.0f / 256.0f;  // 1 / 2^STEPS, STEPS = 8
    const int threads = 256;
    const int blocks = (N_VOX + threads - 1) / threads;

    // iter 0: input (scaled on the fly) -> A
    gridexp_step<0><<<blocks, threads>>>(vel, bufA, scale);
    // iters 1..6: ping-pong A <-> B
    float* cur = bufA;
    float* nxt = bufB;
    for (int i = 1; i <= 6; ++i) {
        gridexp_step<1><<<blocks, threads>>>(cur, nxt, 1.0f);
        float* t = cur; cur = nxt; nxt = t;
    }
    // iter 7: cur -> d_out with identity grid added
    gridexp_step<2><<<blocks, threads>>>(cur, out, 1.0f);
}

// round 2
// speedup vs baseline: 1.1454x; 1.1454x over previous
#include <cuda_runtime.h>
#include <cstdint>

// Problem geometry: velocity (B=2, D=128, H=128, W=128, C=3) float32
#define B_  2
#define DIM 128
#define VOX_PER_B (DIM * DIM * DIM)          // 2097152 = 1<<21
#define N_VOX (B_ * VOX_PER_B)               // 4194304
#define N_ELEM (N_VOX * 3)                   // 12582912

// Ping-pong scratch in padded float4 layout (16 B/voxel): (vz, vy, vx, 0)
__device__ float4 g_bufA[N_VOX];
__device__ float4 g_bufB[N_VOX];

// -------- convert: float3 AoS input -> float4 padded, fused 1/2^STEPS scale --------
__global__ __launch_bounds__(256)
void convert_kernel(const float* __restrict__ in, float4* __restrict__ out, float s)
{
    int t = blockIdx.x * blockDim.x + threadIdx.x;   // one thread = 4 voxels
    if (t >= N_VOX / 4) return;
    const float4* in4 = (const float4*)in;
    float4 a = in4[t * 3 + 0];
    float4 b = in4[t * 3 + 1];
    float4 c = in4[t * 3 + 2];
    out[t * 4 + 0] = make_float4(a.x * s, a.y * s, a.z * s, 0.f);
    out[t * 4 + 1] = make_float4(a.w * s, b.x * s, b.y * s, 0.f);
    out[t * 4 + 2] = make_float4(b.z * s, b.w * s, c.x * s, 0.f);
    out[t * 4 + 3] = make_float4(c.y * s, c.z * s, c.w * s, 0.f);
}

// -------- one squaring step in float4 domain --------
// LAST=0: dst4 (float4 scratch). LAST=1: dst3 (stride-3 output) with identity grid added.
template <int LAST>
__global__ __launch_bounds__(256)
void gridexp_step(const float4* __restrict__ src, float4* __restrict__ dst4,
                  float* __restrict__ dst3)
{
    int idx = blockIdx.x * blockDim.x + threadIdx.x;
    if (idx >= N_VOX) return;

    int b = idx >> 21;
    int r = idx & (VOX_PER_B - 1);
    int z = r >> 14;
    int y = (r >> 7) & 127;
    int x = r & 127;

    float4 v = src[idx];                 // (vz, vy, vx, _)

    float phz = (float)z + v.x;
    float phy = (float)y + v.y;
    float phx = (float)x + v.z;

    float fz = floorf(phz), fy = floorf(phy), fx = floorf(phx);
    float wz1 = phz - fz, wy1 = phy - fy, wx1 = phx - fx;
    float wz0 = 1.0f - wz1, wy0 = 1.0f - wy1, wx0 = 1.0f - wx1;

    int z0 = ((int)fz) & 127, z1 = (z0 + 1) & 127;
    int y0 = ((int)fy) & 127, y1 = (y0 + 1) & 127;
    int x0 = ((int)fx) & 127, x1 = (x0 + 1) & 127;

    int base = b << 21;
    int zo[2] = { z0 << 14, z1 << 14 };
    int yo[2] = { y0 << 7,  y1 << 7  };
    int xo[2] = { x0,       x1       };
    float wz[2] = { wz0, wz1 };
    float wy[2] = { wy0, wy1 };
    float wx[2] = { wx0, wx1 };

    float sz = 0.0f, sy = 0.0f, sx = 0.0f;
#pragma unroll
    for (int a = 0; a < 2; ++a) {
#pragma unroll
        for (int c = 0; c < 2; ++c) {
            float wzy = wz[a] * wy[c];
            int zy = base + zo[a] + yo[c];
#pragma unroll
            for (int d = 0; d < 2; ++d) {
                float4 q = __ldg(src + zy + xo[d]);
                float w = wzy * wx[d];
                sz += w * q.x;
                sy += w * q.y;
                sx += w * q.z;
            }
        }
    }

    float oz = v.x + sz;
    float oy = v.y + sy;
    float ox = v.z + sx;

    if (LAST) {
        float* o = dst3 + (size_t)idx * 3;
        o[0] = oz + (float)z;
        o[1] = oy + (float)y;
        o[2] = ox + (float)x;
    } else {
        dst4[idx] = make_float4(oz, oy, ox, 0.f);
    }
}

extern "C" void kernel_launch(void* const* d_in, const int* in_sizes, int n_in,
                              void* d_out, int out_size)
{
    (void)in_sizes; (void)n_in; (void)out_size;
    const float* vel = (const float*)d_in[0];
    float* out = (float*)d_out;

    float4* bufA = nullptr;
    float4* bufB = nullptr;
    cudaGetSymbolAddress((void**)&bufA, g_bufA);
    cudaGetSymbolAddress((void**)&bufB, g_bufB);

    const float scale = 1.0f / 256.0f;   // 1 / 2^STEPS, STEPS = 8
    const int threads = 256;

    // convert: 4 voxels per thread
    convert_kernel<<<(N_VOX / 4 + threads - 1) / threads, threads>>>(vel, bufA, scale);

    const int blocks = (N_VOX + threads - 1) / threads;
    // 7 middle squaring steps, ping-pong A <-> B
    float4* cur = bufA;
    float4* nxt = bufB;
    for (int i = 0; i < 7; ++i) {
        gridexp_step<0><<<blocks, threads>>>(cur, nxt, nullptr);
        float4* t = cur; cur = nxt; nxt = t;
    }
    // final step: gather from cur, add identity grid, write stride-3 output
    gridexp_step<1><<<blocks, threads>>>(cur, nullptr, out);
}

// round 3
// speedup vs baseline: 1.9506x; 1.7030x over previous
#include <cuda_runtime.h>
#include <cuda_fp16.h>
#include <cstdint>

// Problem geometry: velocity (B=2, D=128, H=128, W=128, C=3) float32
#define B_  2
#define DIM 128
#define VOX_PER_B (DIM * DIM * DIM)          // 2097152 = 1<<21
#define N_VOX (B_ * VOX_PER_B)               // 4194304

// Ping-pong scratch: 8 B/voxel = (half2(vz,vy), half2(vx,0)) packed in uint2
__device__ uint2 g_bufA[N_VOX];
__device__ uint2 g_bufB[N_VOX];

static __device__ __forceinline__ uint2 pack_v(float vz, float vy, float vx)
{
    __half2 h0 = __floats2half2_rn(vz, vy);
    __half2 h1 = __floats2half2_rn(vx, 0.f);
    uint2 r;
    r.x = *(const unsigned int*)&h0;
    r.y = *(const unsigned int*)&h1;
    return r;
}

static __device__ __forceinline__ void unpack_v(uint2 r, float& vz, float& vy, float& vx)
{
    __half2 h0 = *(const __half2*)&r.x;
    __half2 h1 = *(const __half2*)&r.y;
    float2 f0 = __half22float2(h0);
    vz = f0.x; vy = f0.y;
    vx = __low2float(h1);
}

// -------- convert: float3 AoS fp32 input -> packed fp16, fused 1/2^STEPS scale --------
__global__ __launch_bounds__(256)
void convert_kernel(const float* __restrict__ in, uint2* __restrict__ out, float s)
{
    int t = blockIdx.x * blockDim.x + threadIdx.x;   // one thread = 4 voxels
    if (t >= N_VOX / 4) return;
    const float4* in4 = (const float4*)in;
    float4 a = in4[t * 3 + 0];
    float4 b = in4[t * 3 + 1];
    float4 c = in4[t * 3 + 2];
    out[t * 4 + 0] = pack_v(a.x * s, a.y * s, a.z * s);
    out[t * 4 + 1] = pack_v(a.w * s, b.x * s, b.y * s);
    out[t * 4 + 2] = pack_v(b.z * s, b.w * s, c.x * s);
    out[t * 4 + 3] = pack_v(c.y * s, c.z * s, c.w * s);
}

// -------- one squaring step, fp16 storage / fp32 math --------
// LAST=0: dst (packed fp16 scratch). LAST=1: dst3 (stride-3 fp32 output) + identity grid.
template <int LAST>
__global__ __launch_bounds__(256)
void gridexp_step(const uint2* __restrict__ src, uint2* __restrict__ dst,
                  float* __restrict__ dst3)
{
    int idx = blockIdx.x * blockDim.x + threadIdx.x;
    if (idx >= N_VOX) return;

    int b = idx >> 21;
    int r = idx & (VOX_PER_B - 1);
    int z = r >> 14;
    int y = (r >> 7) & 127;
    int x = r & 127;

    float vz, vy, vx;
    unpack_v(src[idx], vz, vy, vx);

    float phz = (float)z + vz;
    float phy = (float)y + vy;
    float phx = (float)x + vx;

    float fz = floorf(phz), fy = floorf(phy), fx = floorf(phx);
    float wz1 = phz - fz, wy1 = phy - fy, wx1 = phx - fx;
    float wz0 = 1.0f - wz1, wy0 = 1.0f - wy1, wx0 = 1.0f - wx1;

    int z0 = ((int)fz) & 127, z1 = (z0 + 1) & 127;
    int y0 = ((int)fy) & 127, y1 = (y0 + 1) & 127;
    int x0 = ((int)fx) & 127, x1 = (x0 + 1) & 127;

    int base = b << 21;
    int zo[2] = { z0 << 14, z1 << 14 };
    int yo[2] = { y0 << 7,  y1 << 7  };
    int xo[2] = { x0,       x1       };
    float wz[2] = { wz0, wz1 };
    float wy[2] = { wy0, wy1 };
    float wx[2] = { wx0, wx1 };

    float sz = 0.0f, sy = 0.0f, sx = 0.0f;
#pragma unroll
    for (int a = 0; a < 2; ++a) {
#pragma unroll
        for (int c = 0; c < 2; ++c) {
            float wzy = wz[a] * wy[c];
            int zy = base + zo[a] + yo[c];
#pragma unroll
            for (int d = 0; d < 2; ++d) {
                uint2 q = __ldg(src + zy + xo[d]);
                float qz, qy, qx;
                unpack_v(q, qz, qy, qx);
                float w = wzy * wx[d];
                sz += w * qz;
                sy += w * qy;
                sx += w * qx;
            }
        }
    }

    float oz = vz + sz;
    float oy = vy + sy;
    float ox = vx + sx;

    if (LAST) {
        float* o = dst3 + (size_t)idx * 3;
        o[0] = oz + (float)z;
        o[1] = oy + (float)y;
        o[2] = ox + (float)x;
    } else {
        dst[idx] = pack_v(oz, oy, ox);
    }
}

extern "C" void kernel_launch(void* const* d_in, const int* in_sizes, int n_in,
                              void* d_out, int out_size)
{
    (void)in_sizes; (void)n_in; (void)out_size;
    const float* vel = (const float*)d_in[0];
    float* out = (float*)d_out;

    uint2* bufA = nullptr;
    uint2* bufB = nullptr;
    cudaGetSymbolAddress((void**)&bufA, g_bufA);
    cudaGetSymbolAddress((void**)&bufB, g_bufB);

    const float scale = 1.0f / 256.0f;   // 1 / 2^STEPS, STEPS = 8
    const int threads = 256;

    convert_kernel<<<(N_VOX / 4 + threads - 1) / threads, threads>>>(vel, bufA, scale);

    const int blocks = (N_VOX + threads - 1) / threads;
    uint2* cur = bufA;
    uint2* nxt = bufB;
    for (int i = 0; i < 7; ++i) {
        gridexp_step<0><<<blocks, threads>>>(cur, nxt, nullptr);
        uint2* t = cur; cur = nxt; nxt = t;
    }
    gridexp_step<1><<<blocks, threads>>>(cur, nullptr, out);
}